// round 6
// baseline (speedup 1.0000x reference)
#include <cuda_runtime.h>

// LSTM persistent kernel for GB300 (sm_103a).
// B=256, T=1024, D=128, H=256, C=10.
// Single persistent kernel: 128 CTAs, software grid barrier per timestep.
// Each CTA owns 8 h-columns (all 4 gates) x 64 batch rows.
// Recurrent+input GEMM fused: Z = [h_prev; x_t] @ [Wh; Wx] (K=384).
// Inner product uses packed fma.rn.f32x2 (FFMA2) for 2x fp32 throughput.
//
// R3 fix: XPAD 37 -> 129. xsh rows are DIM=128 floats; the old stride made
// rows overlap (the entire x contribution was garbage -> rel_err 1.18).
// R5: resubmit unchanged — R4 bench was an infra failure (container died),
// kernel never executed. SMEM 159 KB < 227 KB, 128 CTAs <= 148 SMs @occ1,
// barrier state is launch-reentrant: no hang vector found on re-audit.

#define T_STEPS 1024
#define BATCH   256
#define DIM     128
#define HID     256
#define NCLS    10
#define GRID    128
#define NTHR    128
#define BM      64     // batch rows per CTA
#define HC      8      // h-columns per CTA
#define KTOT    384    // HID + DIM
#define HPAD    68     // hsh row stride (row = 64 floats; even, float4-friendly)
#define XPAD    129    // xsh row stride (row = 128 floats; odd -> 2-way LDS max)
#define ZPAD    33
#define CPAD    9

// Global state (no cudaMalloc allowed): double-buffered h, transposed [j][b].
__device__ float    g_h[2][HID * BATCH];
__device__ unsigned g_count = 0;
__device__ unsigned g_gen   = 0;

__device__ __forceinline__ void grid_barrier(unsigned G) {
    __syncthreads();
    if (threadIdx.x == 0) {
        __threadfence();
        volatile unsigned* genp = &g_gen;
        unsigned my = *genp;
        unsigned arrived = atomicAdd(&g_count, 1u);
        if (arrived == G - 1u) {
            g_count = 0;            // safe: everyone has arrived
            __threadfence();
            atomicExch(&g_gen, my + 1u);
        } else {
            while (*genp == my) { __nanosleep(32); }
            __threadfence();
        }
    }
    __syncthreads();
}

// Accurate activations built on expf (safe even under --use_fast_math;
// avoids tanh.approx whose ~5e-4 abs error could compound over 1024 steps).
__device__ __forceinline__ float fsig(float z) {
    return 1.0f / (1.0f + expf(-z));
}
__device__ __forceinline__ float ftanh(float z) {
    float az = fabsf(z);
    float e  = expf(-2.0f * az);
    float t  = (1.0f - e) / (1.0f + e);
    return copysignf(t, z);
}

__device__ __forceinline__ unsigned long long pack_dup(float a) {
    unsigned long long r;
    asm("mov.b64 %0, {%1, %1};" : "=l"(r) : "f"(a));
    return r;
}
__device__ __forceinline__ void fma2(unsigned long long& acc,
                                     unsigned long long a,
                                     unsigned long long w) {
    asm("fma.rn.f32x2 %0, %1, %2, %0;" : "+l"(acc) : "l"(a), "l"(w));
}
__device__ __forceinline__ void unpack2(unsigned long long v, float& lo, float& hi) {
    asm("mov.b64 {%0, %1}, %2;" : "=f"(lo), "=f"(hi) : "l"(v));
}

__global__ void __launch_bounds__(NTHR, 1) lstm_persistent(
    const float* __restrict__ x,
    const float* __restrict__ wgx, const float* __restrict__ wgh, const float* __restrict__ bg,
    const float* __restrict__ wix, const float* __restrict__ wih, const float* __restrict__ bi,
    const float* __restrict__ wfx, const float* __restrict__ wfh, const float* __restrict__ bf,
    const float* __restrict__ wox, const float* __restrict__ woh, const float* __restrict__ bo,
    const float* __restrict__ wph, const float* __restrict__ bp,
    float* __restrict__ out)
{
    extern __shared__ float smem[];
    float* Wsh = smem;                      // KTOT*32  (48 KB) resident weights
    float* hsh = Wsh + KTOT * 32;           // 256*HPAD staged h_prev (transposed [k][r])
    float* xsh = hsh + HID * HPAD;          // BM*XPAD  staged x_t   (row-major [r][d])
    float* zsh = xsh + BM * XPAD;           // BM*ZPAD
    float* csh = zsh + BM * ZPAD;           // BM*CPAD  persistent cell state
    float* bsh = csh + BM * CPAD;           // 32

    const int tid   = threadIdx.x;
    const int cta   = blockIdx.x;
    const int hj    = cta & 31;            // h-tile index (32 tiles of 8 cols)
    const int bt    = cta >> 5;            // batch tile (4 tiles of 64 rows)
    const int b0    = bt * BM;
    const int jbase = hj * HC;

    const float* Wh[4] = {wgh, wih, wfh, woh};
    const float* Wx[4] = {wgx, wix, wfx, wox};
    const float* Bb[4] = {bg, bi, bf, bo};

    // Load this CTA's 32 weight columns (g0..g7, i0..i7, f0..f7, o0..o7), K=384 rows.
    for (int idx = tid; idx < KTOT * 32; idx += NTHR) {
        int k = idx >> 5, cc = idx & 31;
        int gate = cc >> 3, jj = cc & 7;
        int j = jbase + jj;
        float v = (k < HID) ? Wh[gate][k * HID + j]
                            : Wx[gate][(k - HID) * HID + j];
        Wsh[k * 32 + cc] = v;
    }
    if (tid < 32) {
        int gate = tid >> 3, jj = tid & 7;
        bsh[tid] = Bb[gate][jbase + jj];
    }
    for (int idx = tid; idx < BM * CPAD; idx += NTHR) csh[idx] = 0.0f;
    // Zero our slice of h buffer 0 (h_0 = 0).
    for (int idx = tid; idx < HC * BM; idx += NTHR) {
        int jj = idx >> 6, r = idx & 63;
        g_h[0][(jbase + jj) * BATCH + b0 + r] = 0.0f;
    }
    grid_barrier(gridDim.x);

    // GEMM thread mapping: thread owns 2 rows x 8 cols of the [64 x 32] Z tile.
    const int r0    = 2 * (tid & 31);
    const int cg    = tid >> 5;     // 0..3
    const int cbase = cg * 8;

    for (int t = 0; t < T_STEPS; t++) {
        const int rb = t & 1;

        // ---- stage h_prev (global transposed [j][b] -> hsh[k][r]) ----
        const float* hb = g_h[rb];
        #pragma unroll 8
        for (int i = 0; i < 32; i++) {
            int lin = tid + NTHR * i;
            int k = lin >> 4, rq = lin & 15;
            float4 v = *(const float4*)(hb + k * BATCH + b0 + rq * 4);
            *(float4*)(hsh + k * HPAD + rq * 4) = v;
        }
        // ---- stage x_t (row-major [r][d], scalar stores: XPAD is odd) ----
        const float* xt = x + (size_t)b0 * T_STEPS * DIM + (size_t)t * DIM;
        #pragma unroll 8
        for (int i = 0; i < 16; i++) {
            int lin = tid + NTHR * i;
            int r = lin >> 5, dq = lin & 31;
            float4 v = *(const float4*)(xt + (size_t)r * T_STEPS * DIM + dq * 4);
            float* dst = xsh + r * XPAD + dq * 4;
            dst[0] = v.x; dst[1] = v.y; dst[2] = v.z; dst[3] = v.w;
        }
        __syncthreads();

        // ---- Z = [h; x] @ W + b  via packed FFMA2 ----
        unsigned long long acc[8];
        #pragma unroll
        for (int cp = 0; cp < 4; cp++) {
            unsigned long long bb;
            asm("mov.b64 %0, {%1, %2};" : "=l"(bb)
                : "f"(bsh[cbase + 2 * cp]), "f"(bsh[cbase + 2 * cp + 1]));
            acc[cp] = bb;
            acc[4 + cp] = bb;
        }
        #pragma unroll 4
        for (int k = 0; k < HID; k++) {
            float2 a2 = *(const float2*)(hsh + k * HPAD + r0);
            unsigned long long a0 = pack_dup(a2.x);
            unsigned long long a1 = pack_dup(a2.y);
            const unsigned long long* wp =
                (const unsigned long long*)(Wsh + k * 32 + cbase);
            #pragma unroll
            for (int cp = 0; cp < 4; cp++) {
                unsigned long long w = wp[cp];
                fma2(acc[cp],     a0, w);
                fma2(acc[4 + cp], a1, w);
            }
        }
        #pragma unroll 4
        for (int d = 0; d < DIM; d++) {
            float ax = xsh[r0 * XPAD + d];
            float ay = xsh[(r0 + 1) * XPAD + d];
            unsigned long long a0 = pack_dup(ax);
            unsigned long long a1 = pack_dup(ay);
            const unsigned long long* wp =
                (const unsigned long long*)(Wsh + (HID + d) * 32 + cbase);
            #pragma unroll
            for (int cp = 0; cp < 4; cp++) {
                unsigned long long w = wp[cp];
                fma2(acc[cp],     a0, w);
                fma2(acc[4 + cp], a1, w);
            }
        }
        // Spill Z tile to shared for the gate phase.
        #pragma unroll
        for (int cp = 0; cp < 4; cp++) {
            float lo, hi;
            unpack2(acc[cp], lo, hi);
            zsh[r0 * ZPAD + cbase + 2 * cp]     = lo;
            zsh[r0 * ZPAD + cbase + 2 * cp + 1] = hi;
            unpack2(acc[4 + cp], lo, hi);
            zsh[(r0 + 1) * ZPAD + cbase + 2 * cp]     = lo;
            zsh[(r0 + 1) * ZPAD + cbase + 2 * cp + 1] = hi;
        }
        __syncthreads();

        // ---- gates + state update + write h (coalesced, transposed) ----
        float* hn = g_h[rb ^ 1];
        #pragma unroll
        for (int it = 0; it < 4; it++) {
            int idx = it * NTHR + tid;     // 0..511
            int jj = idx >> 6, r = idx & 63;
            float zg = zsh[r * ZPAD + jj];
            float zi = zsh[r * ZPAD + 8  + jj];
            float zf = zsh[r * ZPAD + 16 + jj];
            float zo = zsh[r * ZPAD + 24 + jj];
            float g  = ftanh(zg);
            float ii = fsig(zi);
            float f  = fsig(zf);
            float o  = fsig(zo);
            float c  = csh[r * CPAD + jj];
            c = g * ii + c * f;
            csh[r * CPAD + jj] = c;
            hn[(jbase + jj) * BATCH + b0 + r] = ftanh(c) * o;
        }
        grid_barrier(gridDim.x);
    }

    // ---- final projection: out = h_T @ wph + bp (h_T lives in buffer 0) ----
    if (hj == 0) {
        const float* hf = g_h[0];
        for (int idx = tid; idx < BM * NCLS; idx += NTHR) {
            int r = idx & 63, cls = idx >> 6;
            float s = bp[cls];
            #pragma unroll 4
            for (int j = 0; j < HID; j++)
                s += hf[j * BATCH + b0 + r] * wph[j * NCLS + cls];
            out[(b0 + r) * NCLS + cls] = s;
        }
    }
}

extern "C" void kernel_launch(void* const* d_in, const int* in_sizes, int n_in,
                              void* d_out, int out_size) {
    const float* xp  = (const float*)d_in[0];
    const float* wgx = (const float*)d_in[1];
    const float* wgh = (const float*)d_in[2];
    const float* bg  = (const float*)d_in[3];
    const float* wix = (const float*)d_in[4];
    const float* wih = (const float*)d_in[5];
    const float* bi  = (const float*)d_in[6];
    const float* wfx = (const float*)d_in[7];
    const float* wfh = (const float*)d_in[8];
    const float* bf  = (const float*)d_in[9];
    const float* wox = (const float*)d_in[10];
    const float* woh = (const float*)d_in[11];
    const float* bo  = (const float*)d_in[12];
    const float* wph = (const float*)d_in[13];
    const float* bp  = (const float*)d_in[14];
    float* out = (float*)d_out;

    const int smem_bytes =
        (KTOT * 32 + HID * HPAD + BM * XPAD + BM * ZPAD + BM * CPAD + 32) *
        (int)sizeof(float);

    cudaFuncSetAttribute(lstm_persistent,
                         cudaFuncAttributeMaxDynamicSharedMemorySize,
                         smem_bytes);

    lstm_persistent<<<GRID, NTHR, smem_bytes>>>(
        xp, wgx, wgh, bg, wix, wih, bi, wfx, wfh, bf, wox, woh, bo,
        wph, bp, out);
}

// round 9
// speedup vs baseline: 1.2327x; 1.2327x over previous
#include <cuda_runtime.h>

// LSTM persistent kernel for GB300 (sm_103a).  R7.
// B=256, T=1024, D=128, H=256, C=10.
// 128 CTAs x 256 threads, software grid barrier per timestep.
// CTA owns 8 h-columns (all 4 gates) x 64 batch rows; Z = [h;x] @ W, K=384.
// R7 changes vs R6 (13327 us, occ 6.2%, issue 22.6% -> latency-bound):
//  - 256 threads with 2-way K-split (k<196 | k>=196): 2 warps/SMSP instead of 1,
//    keeping the 15-instr/8-FFMA2 inner loop. fma pipe becomes binding (~6144
//    cyc/SMSP/step floor).
//  - flag-based grid barrier (per-CTA 128B-strided tokens + CTA0 aggregator)
//    replacing the 128-way contended atomicAdd.
//  - x_{t+1} prestage overlapped with the barrier wait.

#define T_STEPS 1024
#define BATCH   256
#define DIM     128
#define HID     256
#define NCLS    10
#define GRID    128
#define NTHR    256
#define BM      64     // batch rows per CTA
#define HC      8      // h-columns per CTA
#define KTOT    384    // HID + DIM
#define KSPLIT  196    // K split point between thread-halves (load-balanced)
#define HPAD    68     // hsh row stride (row = 64 floats)
#define XPAD    129    // xsh row stride (row = 128 floats; odd -> 2-way LDS max)
#define ZPAD    33
#define CPAD    9

// Global state (no cudaMalloc allowed). All barrier tokens are monotone across
// launches/graph replays: flags and g_gen end each run equal, so the next run
// continues from that value.
__device__ float    g_h[2][HID * BATCH];
__device__ unsigned g_flag[GRID * 32];   // one token per CTA, 128B apart
__device__ unsigned g_gen;

// Accurate activations built on expf (safe even under --use_fast_math).
__device__ __forceinline__ float fsig(float z) {
    return 1.0f / (1.0f + expf(-z));
}
__device__ __forceinline__ float ftanh(float z) {
    float az = fabsf(z);
    float e  = expf(-2.0f * az);
    float t  = (1.0f - e) / (1.0f + e);
    return copysignf(t, z);
}

__device__ __forceinline__ unsigned long long pack_dup(float a) {
    unsigned long long r;
    asm("mov.b64 %0, {%1, %1};" : "=l"(r) : "f"(a));
    return r;
}
__device__ __forceinline__ void fma2(unsigned long long& acc,
                                     unsigned long long a,
                                     unsigned long long w) {
    asm("fma.rn.f32x2 %0, %1, %2, %0;" : "+l"(acc) : "l"(a), "l"(w));
}
__device__ __forceinline__ void unpack2(unsigned long long v, float& lo, float& hi) {
    asm("mov.b64 {%0, %1}, %2;" : "=f"(lo), "=f"(hi) : "l"(v));
}

__global__ void __launch_bounds__(NTHR, 1) lstm_persistent(
    const float* __restrict__ x,
    const float* __restrict__ wgx, const float* __restrict__ wgh, const float* __restrict__ bg,
    const float* __restrict__ wix, const float* __restrict__ wih, const float* __restrict__ bi,
    const float* __restrict__ wfx, const float* __restrict__ wfh, const float* __restrict__ bf,
    const float* __restrict__ wox, const float* __restrict__ woh, const float* __restrict__ bo,
    const float* __restrict__ wph, const float* __restrict__ bp,
    float* __restrict__ out)
{
    extern __shared__ float smem[];
    float* Wsh  = smem;                       // KTOT*32 resident weights
    float* hsh  = Wsh  + KTOT * 32;           // [k][r] staged h_prev
    float* xsh  = hsh  + HID * HPAD;          // [r][d] staged x_t
    float* zsh  = xsh  + BM * XPAD;           // half-0 partial Z
    float* zsh2 = zsh  + BM * ZPAD;           // half-1 partial Z
    float* csh  = zsh2 + BM * ZPAD;           // persistent cell state
    float* bsh  = csh  + BM * CPAD;           // 32 biases

    const int tid   = threadIdx.x;
    const int cta   = blockIdx.x;
    const int hj    = cta & 31;              // h-tile (32 tiles of 8 cols)
    const int bt    = cta >> 5;              // batch tile (4 tiles of 64 rows)
    const int b0    = bt * BM;
    const int jbase = hj * HC;

    const float* Wh[4] = {wgh, wih, wfh, woh};
    const float* Wx[4] = {wgx, wix, wfx, wox};
    const float* Bb[4] = {bg, bi, bf, bo};

    // ---- load resident weights: 32 cols (g0..7,i0..7,f0..7,o0..7) x K=384 ----
    for (int idx = tid; idx < KTOT * 32; idx += NTHR) {
        int k = idx >> 5, cc = idx & 31;
        int gate = cc >> 3, jj = cc & 7;
        int j = jbase + jj;
        float v = (k < HID) ? Wh[gate][k * HID + j]
                            : Wx[gate][(k - HID) * HID + j];
        Wsh[k * 32 + cc] = v;
    }
    if (tid < 32) {
        int gate = tid >> 3, jj = tid & 7;
        bsh[tid] = Bb[gate][jbase + jj];
    }
    for (int idx = tid; idx < BM * CPAD; idx += NTHR) csh[idx] = 0.0f;
    for (int idx = tid; idx < HC * BM; idx += NTHR) {
        int jj = idx >> 6, r = idx & 63;
        g_h[0][(jbase + jj) * BATCH + b0 + r] = 0.0f;
    }
    // prestage x_0
    {
        const float* xt = x + (size_t)b0 * T_STEPS * DIM;
        #pragma unroll 8
        for (int i = 0; i < 8; i++) {
            int lin = tid + NTHR * i;
            int r = lin >> 5, dq = lin & 31;
            float4 v = *(const float4*)(xt + (size_t)r * T_STEPS * DIM + dq * 4);
            float* dst = xsh + r * XPAD + dq * 4;
            dst[0] = v.x; dst[1] = v.y; dst[2] = v.z; dst[3] = v.w;
        }
    }

    // Barrier token base: g_gen is only advanced after every CTA arrives at a
    // barrier, so every CTA reads the same V0 here.
    unsigned bar = *(volatile unsigned*)&g_gen;

    // ---- init grid barrier (flag-based) ----
    {
        bar++;
        __syncthreads();
        if (tid == 0) { __threadfence(); *(volatile unsigned*)&g_flag[cta * 32] = bar; }
        if (cta == 0) {
            if (tid < 32) {
                for (;;) {
                    unsigned m0 = *(volatile unsigned*)&g_flag[(tid      ) * 32];
                    unsigned m1 = *(volatile unsigned*)&g_flag[(tid + 32 ) * 32];
                    unsigned m2 = *(volatile unsigned*)&g_flag[(tid + 64 ) * 32];
                    unsigned m3 = *(volatile unsigned*)&g_flag[(tid + 96 ) * 32];
                    bool ok = (m0 >= bar) && (m1 >= bar) && (m2 >= bar) && (m3 >= bar);
                    if (__all_sync(0xffffffffu, ok)) break;
                    __nanosleep(32);
                }
                if (tid == 0) { __threadfence(); *(volatile unsigned*)&g_gen = bar; }
            }
        } else if (tid == 0) {
            while (*(volatile unsigned*)&g_gen < bar) __nanosleep(32);
            __threadfence();
        }
        __syncthreads();
    }

    // ---- GEMM thread mapping: two K-halves, each covering the 64x32 Z tile ----
    // half 0: warps 0-3, k in [0, KSPLIT); half 1: warps 4-7, k in [KSPLIT, 384).
    const int half  = tid >> 7;
    const int htid  = tid & 127;
    const int r0    = 2 * (htid & 31);
    const int cg    = htid >> 5;            // 0..3
    const int cbase = cg * 8;
    float* zmine = half ? zsh2 : zsh;

    for (int t = 0; t < T_STEPS; t++) {
        const int rb = t & 1;

        // ---- stage h_prev (global [j][b] -> hsh[k][r]) ----
        const float* hb = g_h[rb];
        #pragma unroll 8
        for (int i = 0; i < 16; i++) {
            int lin = tid + NTHR * i;
            int k = lin >> 4, rq = lin & 15;
            float4 v = *(const float4*)(hb + k * BATCH + b0 + rq * 4);
            *(float4*)(hsh + k * HPAD + rq * 4) = v;
        }
        __syncthreads();

        // ---- partial Z over this half's K range ----
        unsigned long long acc[8];
        if (half == 0) {
            #pragma unroll
            for (int cp = 0; cp < 4; cp++) {
                unsigned long long bb;
                asm("mov.b64 %0, {%1, %2};" : "=l"(bb)
                    : "f"(bsh[cbase + 2 * cp]), "f"(bsh[cbase + 2 * cp + 1]));
                acc[cp] = bb;
                acc[4 + cp] = bb;
            }
        } else {
            #pragma unroll
            for (int cp = 0; cp < 8; cp++) acc[cp] = 0ull;
        }

        const int klo = half ? KSPLIT : 0;
        const int khi = half ? HID    : KSPLIT;
        #pragma unroll 4
        for (int k = klo; k < khi; k++) {
            float2 a2 = *(const float2*)(hsh + k * HPAD + r0);
            unsigned long long a0 = pack_dup(a2.x);
            unsigned long long a1 = pack_dup(a2.y);
            const unsigned long long* wp =
                (const unsigned long long*)(Wsh + k * 32 + cbase);
            #pragma unroll
            for (int cp = 0; cp < 4; cp++) {
                unsigned long long w = wp[cp];
                fma2(acc[cp],     a0, w);
                fma2(acc[4 + cp], a1, w);
            }
        }
        if (half) {
            #pragma unroll 4
            for (int d = 0; d < DIM; d++) {
                float ax = xsh[r0 * XPAD + d];
                float ay = xsh[(r0 + 1) * XPAD + d];
                unsigned long long a0 = pack_dup(ax);
                unsigned long long a1 = pack_dup(ay);
                const unsigned long long* wp =
                    (const unsigned long long*)(Wsh + (HID + d) * 32 + cbase);
                #pragma unroll
                for (int cp = 0; cp < 4; cp++) {
                    unsigned long long w = wp[cp];
                    fma2(acc[cp],     a0, w);
                    fma2(acc[4 + cp], a1, w);
                }
            }
        }
        // spill partial Z
        #pragma unroll
        for (int cp = 0; cp < 4; cp++) {
            float lo, hi;
            unpack2(acc[cp], lo, hi);
            zmine[r0 * ZPAD + cbase + 2 * cp]     = lo;
            zmine[r0 * ZPAD + cbase + 2 * cp + 1] = hi;
            unpack2(acc[4 + cp], lo, hi);
            zmine[(r0 + 1) * ZPAD + cbase + 2 * cp]     = lo;
            zmine[(r0 + 1) * ZPAD + cbase + 2 * cp + 1] = hi;
        }
        __syncthreads();

        // ---- gates + state update + write h (coalesced, transposed) ----
        float* hn = g_h[rb ^ 1];
        #pragma unroll
        for (int it = 0; it < 2; it++) {
            int idx = it * NTHR + tid;     // 0..511
            int jj = idx >> 6, r = idx & 63;
            float zg = zsh[r * ZPAD + jj]      + zsh2[r * ZPAD + jj];
            float zi = zsh[r * ZPAD + 8  + jj] + zsh2[r * ZPAD + 8  + jj];
            float zf = zsh[r * ZPAD + 16 + jj] + zsh2[r * ZPAD + 16 + jj];
            float zo = zsh[r * ZPAD + 24 + jj] + zsh2[r * ZPAD + 24 + jj];
            float g  = ftanh(zg);
            float ii = fsig(zi);
            float f  = fsig(zf);
            float o  = fsig(zo);
            float c  = csh[r * CPAD + jj];
            c = g * ii + c * f;
            csh[r * CPAD + jj] = c;
            hn[(jbase + jj) * BATCH + b0 + r] = ftanh(c) * o;
        }

        // ---- grid barrier with x_{t+1} prestage overlapped ----
        bar++;
        __syncthreads();                      // all h/z/c writes done CTA-wide
        if (tid == 0) { __threadfence(); *(volatile unsigned*)&g_flag[cta * 32] = bar; }
        // prestage next x while other CTAs finish (xsh is dead: GEMM reads
        // ended at the post-GEMM __syncthreads above)
        if (t + 1 < T_STEPS) {
            const float* xt = x + (size_t)b0 * T_STEPS * DIM + (size_t)(t + 1) * DIM;
            #pragma unroll 8
            for (int i = 0; i < 8; i++) {
                int lin = tid + NTHR * i;
                int r = lin >> 5, dq = lin & 31;
                float4 v = *(const float4*)(xt + (size_t)r * T_STEPS * DIM + dq * 4);
                float* dst = xsh + r * XPAD + dq * 4;
                dst[0] = v.x; dst[1] = v.y; dst[2] = v.z; dst[3] = v.w;
            }
        }
        if (cta == 0) {
            if (tid < 32) {
                for (;;) {
                    unsigned m0 = *(volatile unsigned*)&g_flag[(tid      ) * 32];
                    unsigned m1 = *(volatile unsigned*)&g_flag[(tid + 32 ) * 32];
                    unsigned m2 = *(volatile unsigned*)&g_flag[(tid + 64 ) * 32];
                    unsigned m3 = *(volatile unsigned*)&g_flag[(tid + 96 ) * 32];
                    bool ok = (m0 >= bar) && (m1 >= bar) && (m2 >= bar) && (m3 >= bar);
                    if (__all_sync(0xffffffffu, ok)) break;
                    __nanosleep(32);
                }
                if (tid == 0) { __threadfence(); *(volatile unsigned*)&g_gen = bar; }
            }
        } else if (tid == 0) {
            while (*(volatile unsigned*)&g_gen < bar) __nanosleep(32);
            __threadfence();
        }
        __syncthreads();
    }

    // ---- final projection: out = h_T @ wph + bp (h_T is in buffer 0) ----
    if (hj == 0) {
        const float* hf = g_h[0];
        for (int idx = tid; idx < BM * NCLS; idx += NTHR) {
            int r = idx & 63, cls = idx >> 6;
            float s = bp[cls];
            #pragma unroll 4
            for (int j = 0; j < HID; j++)
                s += hf[j * BATCH + b0 + r] * wph[j * NCLS + cls];
            out[(b0 + r) * NCLS + cls] = s;
        }
    }
}

extern "C" void kernel_launch(void* const* d_in, const int* in_sizes, int n_in,
                              void* d_out, int out_size) {
    const float* xp  = (const float*)d_in[0];
    const float* wgx = (const float*)d_in[1];
    const float* wgh = (const float*)d_in[2];
    const float* bg  = (const float*)d_in[3];
    const float* wix = (const float*)d_in[4];
    const float* wih = (const float*)d_in[5];
    const float* bi  = (const float*)d_in[6];
    const float* wfx = (const float*)d_in[7];
    const float* wfh = (const float*)d_in[8];
    const float* bf  = (const float*)d_in[9];
    const float* wox = (const float*)d_in[10];
    const float* woh = (const float*)d_in[11];
    const float* bo  = (const float*)d_in[12];
    const float* wph = (const float*)d_in[13];
    const float* bp  = (const float*)d_in[14];
    float* out = (float*)d_out;

    const int smem_bytes =
        (KTOT * 32 + HID * HPAD + BM * XPAD + 2 * BM * ZPAD + BM * CPAD + 32) *
        (int)sizeof(float);

    cudaFuncSetAttribute(lstm_persistent,
                         cudaFuncAttributeMaxDynamicSharedMemorySize,
                         smem_bytes);

    lstm_persistent<<<GRID, NTHR, smem_bytes>>>(
        xp, wgx, wgh, bg, wix, wih, bi, wfx, wfh, bf, wox, woh, bo,
        wph, bp, out);
}

// round 10
// speedup vs baseline: 1.2993x; 1.0541x over previous
#include <cuda_runtime.h>

// LSTM persistent kernel for GB300 (sm_103a).  R10.
// B=256, T=1024, D=128, H=256, C=10.
// 128 CTAs x 512 threads, software grid barrier per timestep.
// CTA owns 8 h-columns (all 4 gates) x 64 batch rows; Z = [h;x] @ W, K=384.
// R10 vs R7 (10811 us, occ 12.5%, issue 29.4%, fma 28% -> still latency-bound):
//  - 512 threads, 4-way K-split (96 k-rows per quarter) -> 4 warps/SMSP to
//    cover LDS/LDG latency; FFMA2 pipe floor (~6.2k cyc/SMSP/step) unchanged
//    but now approachable.
//  - 4 partial-Z buffers (+33KB smem -> 188KB, still 1 CTA/SM).
//  - staging/gates phases get 2x threads (serial tails halve).

#define T_STEPS 1024
#define BATCH   256
#define DIM     128
#define HID     256
#define NCLS    10
#define GRID    128
#define NTHR    512
#define BM      64     // batch rows per CTA
#define HC      8      // h-columns per CTA
#define KTOT    384    // HID + DIM
#define KQ      96     // K rows per quarter
#define HPAD    68     // hsh row stride (row = 64 floats)
#define XPAD    129    // xsh row stride (row = 128 floats; odd -> 2-way LDS max)
#define ZPAD    33
#define CPAD    9

// Global state (no cudaMalloc allowed). Barrier tokens are monotone across
// launches/graph replays: flags and g_gen end each run equal.
__device__ float    g_h[2][HID * BATCH];
__device__ unsigned g_flag[GRID * 32];   // one token per CTA, 128B apart
__device__ unsigned g_gen;

// Accurate activations built on expf (safe even under --use_fast_math).
__device__ __forceinline__ float fsig(float z) {
    return 1.0f / (1.0f + expf(-z));
}
__device__ __forceinline__ float ftanh(float z) {
    float az = fabsf(z);
    float e  = expf(-2.0f * az);
    float t  = (1.0f - e) / (1.0f + e);
    return copysignf(t, z);
}

__device__ __forceinline__ unsigned long long pack_dup(float a) {
    unsigned long long r;
    asm("mov.b64 %0, {%1, %1};" : "=l"(r) : "f"(a));
    return r;
}
__device__ __forceinline__ void fma2(unsigned long long& acc,
                                     unsigned long long a,
                                     unsigned long long w) {
    asm("fma.rn.f32x2 %0, %1, %2, %0;" : "+l"(acc) : "l"(a), "l"(w));
}
__device__ __forceinline__ void unpack2(unsigned long long v, float& lo, float& hi) {
    asm("mov.b64 {%0, %1}, %2;" : "=f"(lo), "=f"(hi) : "l"(v));
}

__global__ void __launch_bounds__(NTHR, 1) lstm_persistent(
    const float* __restrict__ x,
    const float* __restrict__ wgx, const float* __restrict__ wgh, const float* __restrict__ bg,
    const float* __restrict__ wix, const float* __restrict__ wih, const float* __restrict__ bi,
    const float* __restrict__ wfx, const float* __restrict__ wfh, const float* __restrict__ bf,
    const float* __restrict__ wox, const float* __restrict__ woh, const float* __restrict__ bo,
    const float* __restrict__ wph, const float* __restrict__ bp,
    float* __restrict__ out)
{
    extern __shared__ float smem[];
    float* Wsh  = smem;                       // KTOT*32 resident weights
    float* hsh  = Wsh  + KTOT * 32;           // [k][r] staged h_prev
    float* xsh  = hsh  + HID * HPAD;          // [r][d] staged x_t
    float* zq0  = xsh  + BM * XPAD;           // quarter partial Z buffers
    float* zq1  = zq0  + BM * ZPAD;
    float* zq2  = zq1  + BM * ZPAD;
    float* zq3  = zq2  + BM * ZPAD;
    float* csh  = zq3  + BM * ZPAD;           // persistent cell state
    float* bsh  = csh  + BM * CPAD;           // 32 biases

    const int tid   = threadIdx.x;
    const int cta   = blockIdx.x;
    const int hj    = cta & 31;              // h-tile (32 tiles of 8 cols)
    const int bt    = cta >> 5;              // batch tile (4 tiles of 64 rows)
    const int b0    = bt * BM;
    const int jbase = hj * HC;

    const float* Wh[4] = {wgh, wih, wfh, woh};
    const float* Wx[4] = {wgx, wix, wfx, wox};
    const float* Bb[4] = {bg, bi, bf, bo};

    // ---- load resident weights: 32 cols (g0..7,i0..7,f0..7,o0..7) x K=384 ----
    for (int idx = tid; idx < KTOT * 32; idx += NTHR) {
        int k = idx >> 5, cc = idx & 31;
        int gate = cc >> 3, jj = cc & 7;
        int j = jbase + jj;
        float v = (k < HID) ? Wh[gate][k * HID + j]
                            : Wx[gate][(k - HID) * HID + j];
        Wsh[k * 32 + cc] = v;
    }
    if (tid < 32) {
        int gate = tid >> 3, jj = tid & 7;
        bsh[tid] = Bb[gate][jbase + jj];
    }
    for (int idx = tid; idx < BM * CPAD; idx += NTHR) csh[idx] = 0.0f;
    for (int idx = tid; idx < HC * BM; idx += NTHR) {
        int jj = idx >> 6, r = idx & 63;
        g_h[0][(jbase + jj) * BATCH + b0 + r] = 0.0f;
    }
    // prestage x_0
    {
        const float* xt = x + (size_t)b0 * T_STEPS * DIM;
        #pragma unroll 4
        for (int i = 0; i < 4; i++) {
            int lin = tid + NTHR * i;
            int r = lin >> 5, dq = lin & 31;
            float4 v = *(const float4*)(xt + (size_t)r * T_STEPS * DIM + dq * 4);
            float* dst = xsh + r * XPAD + dq * 4;
            dst[0] = v.x; dst[1] = v.y; dst[2] = v.z; dst[3] = v.w;
        }
    }

    // Barrier token base (g_gen advances only when every CTA has arrived).
    unsigned bar = *(volatile unsigned*)&g_gen;

    // ---- init grid barrier (flag-based) ----
    {
        bar++;
        __syncthreads();
        if (tid == 0) { __threadfence(); *(volatile unsigned*)&g_flag[cta * 32] = bar; }
        if (cta == 0) {
            if (tid < 32) {
                for (;;) {
                    unsigned m0 = *(volatile unsigned*)&g_flag[(tid      ) * 32];
                    unsigned m1 = *(volatile unsigned*)&g_flag[(tid + 32 ) * 32];
                    unsigned m2 = *(volatile unsigned*)&g_flag[(tid + 64 ) * 32];
                    unsigned m3 = *(volatile unsigned*)&g_flag[(tid + 96 ) * 32];
                    bool ok = (m0 >= bar) && (m1 >= bar) && (m2 >= bar) && (m3 >= bar);
                    if (__all_sync(0xffffffffu, ok)) break;
                    __nanosleep(32);
                }
                if (tid == 0) { __threadfence(); *(volatile unsigned*)&g_gen = bar; }
            }
        } else if (tid == 0) {
            while (*(volatile unsigned*)&g_gen < bar) __nanosleep(32);
            __threadfence();
        }
        __syncthreads();
    }

    // ---- GEMM mapping: 4 K-quarters, each covering the full 64x32 Z tile ----
    // quarter q handles global k in [96q, 96(q+1)):
    //   q0: h[0,96)   q1: h[96,192)   q2: h[192,256)+x[0,32)   q3: x[32,128)
    const int q     = tid >> 7;             // 0..3
    const int htid  = tid & 127;
    const int r0    = 2 * (htid & 31);
    const int cg    = htid >> 5;            // 0..3
    const int cbase = cg * 8;
    float* zquart[4] = {zq0, zq1, zq2, zq3};
    float* zmine = zquart[q];
    const int klo_h = KQ * q;
    const int khi_h = (KQ * (q + 1) < HID) ? KQ * (q + 1) : HID;
    const int dlo   = (KQ * q       > HID) ? KQ * q       - HID : 0;
    const int dhi   = (KQ * (q + 1) > HID) ? KQ * (q + 1) - HID : 0;

    for (int t = 0; t < T_STEPS; t++) {
        const int rb = t & 1;

        // ---- stage h_prev (global [j][b] -> hsh[k][r]) ----
        const float* hb = g_h[rb];
        #pragma unroll 8
        for (int i = 0; i < 8; i++) {
            int lin = tid + NTHR * i;
            int k = lin >> 4, rq = lin & 15;
            float4 v = *(const float4*)(hb + k * BATCH + b0 + rq * 4);
            *(float4*)(hsh + k * HPAD + rq * 4) = v;
        }
        __syncthreads();

        // ---- partial Z over this quarter's K range ----
        unsigned long long acc[8];
        if (q == 0) {
            #pragma unroll
            for (int cp = 0; cp < 4; cp++) {
                unsigned long long bb;
                asm("mov.b64 %0, {%1, %2};" : "=l"(bb)
                    : "f"(bsh[cbase + 2 * cp]), "f"(bsh[cbase + 2 * cp + 1]));
                acc[cp] = bb;
                acc[4 + cp] = bb;
            }
        } else {
            #pragma unroll
            for (int cp = 0; cp < 8; cp++) acc[cp] = 0ull;
        }

        #pragma unroll 4
        for (int k = klo_h; k < khi_h; k++) {
            float2 a2 = *(const float2*)(hsh + k * HPAD + r0);
            unsigned long long a0 = pack_dup(a2.x);
            unsigned long long a1 = pack_dup(a2.y);
            const unsigned long long* wp =
                (const unsigned long long*)(Wsh + k * 32 + cbase);
            #pragma unroll
            for (int cp = 0; cp < 4; cp++) {
                unsigned long long w = wp[cp];
                fma2(acc[cp],     a0, w);
                fma2(acc[4 + cp], a1, w);
            }
        }
        #pragma unroll 4
        for (int d = dlo; d < dhi; d++) {
            float ax = xsh[r0 * XPAD + d];
            float ay = xsh[(r0 + 1) * XPAD + d];
            unsigned long long a0 = pack_dup(ax);
            unsigned long long a1 = pack_dup(ay);
            const unsigned long long* wp =
                (const unsigned long long*)(Wsh + (HID + d) * 32 + cbase);
            #pragma unroll
            for (int cp = 0; cp < 4; cp++) {
                unsigned long long w = wp[cp];
                fma2(acc[cp],     a0, w);
                fma2(acc[4 + cp], a1, w);
            }
        }
        // spill partial Z
        #pragma unroll
        for (int cp = 0; cp < 4; cp++) {
            float lo, hi;
            unpack2(acc[cp], lo, hi);
            zmine[r0 * ZPAD + cbase + 2 * cp]     = lo;
            zmine[r0 * ZPAD + cbase + 2 * cp + 1] = hi;
            unpack2(acc[4 + cp], lo, hi);
            zmine[(r0 + 1) * ZPAD + cbase + 2 * cp]     = lo;
            zmine[(r0 + 1) * ZPAD + cbase + 2 * cp + 1] = hi;
        }
        __syncthreads();

        // ---- gates + state update + write h (coalesced, transposed) ----
        float* hn = g_h[rb ^ 1];
        {
            int idx = tid;                   // 512 = 8 cols x 64 rows
            int jj = idx >> 6, r = idx & 63;
            float zg = zq0[r * ZPAD + jj]      + zq1[r * ZPAD + jj]
                     + zq2[r * ZPAD + jj]      + zq3[r * ZPAD + jj];
            float zi = zq0[r * ZPAD + 8  + jj] + zq1[r * ZPAD + 8  + jj]
                     + zq2[r * ZPAD + 8  + jj] + zq3[r * ZPAD + 8  + jj];
            float zf = zq0[r * ZPAD + 16 + jj] + zq1[r * ZPAD + 16 + jj]
                     + zq2[r * ZPAD + 16 + jj] + zq3[r * ZPAD + 16 + jj];
            float zo = zq0[r * ZPAD + 24 + jj] + zq1[r * ZPAD + 24 + jj]
                     + zq2[r * ZPAD + 24 + jj] + zq3[r * ZPAD + 24 + jj];
            float g  = ftanh(zg);
            float ii = fsig(zi);
            float f  = fsig(zf);
            float o  = fsig(zo);
            float c  = csh[r * CPAD + jj];
            c = g * ii + c * f;
            csh[r * CPAD + jj] = c;
            hn[(jbase + jj) * BATCH + b0 + r] = ftanh(c) * o;
        }

        // ---- grid barrier with x_{t+1} prestage overlapped ----
        bar++;
        __syncthreads();                      // all h/z/c writes done CTA-wide
        if (tid == 0) { __threadfence(); *(volatile unsigned*)&g_flag[cta * 32] = bar; }
        // prestage next x while other CTAs finish (xsh dead since post-GEMM sync)
        if (t + 1 < T_STEPS) {
            const float* xt = x + (size_t)b0 * T_STEPS * DIM + (size_t)(t + 1) * DIM;
            #pragma unroll 4
            for (int i = 0; i < 4; i++) {
                int lin = tid + NTHR * i;
                int r = lin >> 5, dq = lin & 31;
                float4 v = *(const float4*)(xt + (size_t)r * T_STEPS * DIM + dq * 4);
                float* dst = xsh + r * XPAD + dq * 4;
                dst[0] = v.x; dst[1] = v.y; dst[2] = v.z; dst[3] = v.w;
            }
        }
        if (cta == 0) {
            if (tid < 32) {
                for (;;) {
                    unsigned m0 = *(volatile unsigned*)&g_flag[(tid      ) * 32];
                    unsigned m1 = *(volatile unsigned*)&g_flag[(tid + 32 ) * 32];
                    unsigned m2 = *(volatile unsigned*)&g_flag[(tid + 64 ) * 32];
                    unsigned m3 = *(volatile unsigned*)&g_flag[(tid + 96 ) * 32];
                    bool ok = (m0 >= bar) && (m1 >= bar) && (m2 >= bar) && (m3 >= bar);
                    if (__all_sync(0xffffffffu, ok)) break;
                    __nanosleep(32);
                }
                if (tid == 0) { __threadfence(); *(volatile unsigned*)&g_gen = bar; }
            }
        } else if (tid == 0) {
            while (*(volatile unsigned*)&g_gen < bar) __nanosleep(32);
            __threadfence();
        }
        __syncthreads();
    }

    // ---- final projection: out = h_T @ wph + bp (h_T is in buffer 0) ----
    if (hj == 0) {
        const float* hf = g_h[0];
        for (int idx = tid; idx < BM * NCLS; idx += NTHR) {
            int r = idx & 63, cls = idx >> 6;
            float s = bp[cls];
            #pragma unroll 4
            for (int j = 0; j < HID; j++)
                s += hf[j * BATCH + b0 + r] * wph[j * NCLS + cls];
            out[(b0 + r) * NCLS + cls] = s;
        }
    }
}

extern "C" void kernel_launch(void* const* d_in, const int* in_sizes, int n_in,
                              void* d_out, int out_size) {
    const float* xp  = (const float*)d_in[0];
    const float* wgx = (const float*)d_in[1];
    const float* wgh = (const float*)d_in[2];
    const float* bg  = (const float*)d_in[3];
    const float* wix = (const float*)d_in[4];
    const float* wih = (const float*)d_in[5];
    const float* bi  = (const float*)d_in[6];
    const float* wfx = (const float*)d_in[7];
    const float* wfh = (const float*)d_in[8];
    const float* bf  = (const float*)d_in[9];
    const float* wox = (const float*)d_in[10];
    const float* woh = (const float*)d_in[11];
    const float* bo  = (const float*)d_in[12];
    const float* wph = (const float*)d_in[13];
    const float* bp  = (const float*)d_in[14];
    float* out = (float*)d_out;

    const int smem_bytes =
        (KTOT * 32 + HID * HPAD + BM * XPAD + 4 * BM * ZPAD + BM * CPAD + 32) *
        (int)sizeof(float);

    cudaFuncSetAttribute(lstm_persistent,
                         cudaFuncAttributeMaxDynamicSharedMemorySize,
                         smem_bytes);

    lstm_persistent<<<GRID, NTHR, smem_bytes>>>(
        xp, wgx, wgh, bg, wix, wih, bi, wfx, wfh, bf, wox, woh, bo,
        wph, bp, out);
}